// round 1
// baseline (speedup 1.0000x reference)
#include <cuda_runtime.h>
#include <mma.h>
using namespace nvcuda;

// Problem constants (fixed by the reference)
#define BT      4096      // B * T_dec = B * T_enc = 2 * 2048
#define DM      1024      // d_model
#define NHEADS  16
#define DH      64
#define TDEC    2048
#define TENC    2048
#define NB      2

// Scratch (allocation-free): Q, K, V, Y buffers, each (4096 x 1024) fp32
__device__ float g_Q[BT * DM];
__device__ float g_K[BT * DM];
__device__ float g_V[BT * DM];
__device__ float g_Y[BT * DM];

// ---------------------------------------------------------------------------
// TF32 tiled GEMM: C = X @ W   (X: MxK row-major, W: KxN row-major)
// Block tile 128x128x16, 256 threads = 8 warps (4x2), warp tile 32x64.
// ---------------------------------------------------------------------------
__global__ __launch_bounds__(256) void gemm_tf32_kernel(
    const float* __restrict__ X, const float* __restrict__ W,
    float* __restrict__ C, int M, int N, int K)
{
    const int BM = 128, BN = 128, BK = 16;
    const int LDA = 24;    // 16 + 8 pad
    const int LDB = 136;   // 128 + 8 pad
    __shared__ float As[128 * LDA];
    __shared__ float Bs[16 * LDB];

    const int bm = blockIdx.y * BM;
    const int bn = blockIdx.x * BN;
    const int tid = threadIdx.x;
    const int warp = tid >> 5;
    const int wm = warp >> 1;   // 0..3 -> row block of 32
    const int wn = warp & 1;    // 0..1 -> col block of 64

    wmma::fragment<wmma::accumulator, 16, 16, 8, float> acc[2][4];
    #pragma unroll
    for (int i = 0; i < 2; i++)
        #pragma unroll
        for (int j = 0; j < 4; j++)
            wmma::fill_fragment(acc[i][j], 0.0f);

    for (int k0 = 0; k0 < K; k0 += BK) {
        // Load A tile: 128 x 16  (512 float4, 2 per thread)
        #pragma unroll
        for (int i = tid; i < 512; i += 256) {
            int row = i >> 2, c4 = i & 3;
            float4 v = *reinterpret_cast<const float4*>(
                &X[(size_t)(bm + row) * K + k0 + c4 * 4]);
            float* dst = &As[row * LDA + c4 * 4];
            dst[0] = v.x; dst[1] = v.y; dst[2] = v.z; dst[3] = v.w;
        }
        // Load B tile: 16 x 128  (512 float4, 2 per thread)
        #pragma unroll
        for (int i = tid; i < 512; i += 256) {
            int row = i >> 5, c4 = i & 31;
            float4 v = *reinterpret_cast<const float4*>(
                &W[(size_t)(k0 + row) * N + bn + c4 * 4]);
            float* dst = &Bs[row * LDB + c4 * 4];
            dst[0] = v.x; dst[1] = v.y; dst[2] = v.z; dst[3] = v.w;
        }
        __syncthreads();

        #pragma unroll
        for (int kk = 0; kk < BK; kk += 8) {
            wmma::fragment<wmma::matrix_a, 16, 16, 8, wmma::precision::tf32, wmma::row_major> afr[2];
            wmma::fragment<wmma::matrix_b, 16, 16, 8, wmma::precision::tf32, wmma::row_major> bfr[4];
            #pragma unroll
            for (int mt = 0; mt < 2; mt++) {
                wmma::load_matrix_sync(afr[mt], &As[(wm * 32 + mt * 16) * LDA + kk], LDA);
                #pragma unroll
                for (int e = 0; e < afr[mt].num_elements; e++)
                    afr[mt].x[e] = wmma::__float_to_tf32(afr[mt].x[e]);
            }
            #pragma unroll
            for (int nt = 0; nt < 4; nt++) {
                wmma::load_matrix_sync(bfr[nt], &Bs[kk * LDB + wn * 64 + nt * 16], LDB);
                #pragma unroll
                for (int e = 0; e < bfr[nt].num_elements; e++)
                    bfr[nt].x[e] = wmma::__float_to_tf32(bfr[nt].x[e]);
            }
            #pragma unroll
            for (int mt = 0; mt < 2; mt++)
                #pragma unroll
                for (int nt = 0; nt < 4; nt++)
                    wmma::mma_sync(acc[mt][nt], afr[mt], bfr[nt], acc[mt][nt]);
        }
        __syncthreads();
    }

    #pragma unroll
    for (int mt = 0; mt < 2; mt++)
        #pragma unroll
        for (int nt = 0; nt < 4; nt++)
            wmma::store_matrix_sync(
                &C[(size_t)(bm + wm * 32 + mt * 16) * N + bn + wn * 64 + nt * 16],
                acc[mt][nt], N, wmma::mem_row_major);
}

// ---------------------------------------------------------------------------
// Bias add: C[m][n] += b[n]  (N = 1024, power of two)
// ---------------------------------------------------------------------------
__global__ void bias_kernel(float* __restrict__ C, const float* __restrict__ b, int total)
{
    for (int idx = blockIdx.x * blockDim.x + threadIdx.x; idx < total;
         idx += gridDim.x * blockDim.x)
        C[idx] += b[idx & (DM - 1)];
}

// ---------------------------------------------------------------------------
// Flash attention (TF32 wmma). One block = one (b,h) x 64 query rows.
// grid = (TDEC/64, B*NHEADS), 256 threads = 8 warps.
// ---------------------------------------------------------------------------
#define ATT_LD 72   // 64 + 8 pad
#define ATT_SMEM_BYTES ((5 * 64 * ATT_LD + 128) * 4)

__global__ __launch_bounds__(256) void attn_kernel(
    const float* __restrict__ Q, const float* __restrict__ K,
    const float* __restrict__ V, float* __restrict__ Y)
{
    extern __shared__ float sm[];
    float* Qs = sm;                    // 64 x ATT_LD
    float* Ks = Qs + 64 * ATT_LD;
    float* Vs = Ks + 64 * ATT_LD;
    float* Ss = Vs + 64 * ATT_LD;      // scores / probabilities
    float* Os = Ss + 64 * ATT_LD;      // output accumulator
    float* m_s = Os + 64 * ATT_LD;     // 64 row maxima
    float* l_s = m_s + 64;             // 64 row sums

    const int bh = blockIdx.y;
    const int b  = bh >> 4;            // NHEADS = 16
    const int h  = bh & 15;
    const int q0 = blockIdx.x * 64;
    const int tid = threadIdx.x;
    const int warp = tid >> 5;
    const int wm = warp >> 1;          // 0..3 -> 16-row stripe
    const int wn = warp & 1;           // 0..1 -> 32-col half
    const float scale = 0.125f;        // 1/sqrt(64)

    // Load Q tile (64x64), pre-scaled. 1024 float4, 4 per thread.
    #pragma unroll
    for (int i = tid; i < 1024; i += 256) {
        int row = i >> 4, c4 = i & 15;
        float4 v = *reinterpret_cast<const float4*>(
            &Q[(size_t)(b * TDEC + q0 + row) * DM + h * DH + c4 * 4]);
        float* dst = &Qs[row * ATT_LD + c4 * 4];
        dst[0] = v.x * scale; dst[1] = v.y * scale;
        dst[2] = v.z * scale; dst[3] = v.w * scale;
    }
    // Init O accumulator + stats
    {
        int r = tid >> 2, seg = tid & 3;
        float* Or = &Os[r * ATT_LD + seg * 16];
        #pragma unroll
        for (int c = 0; c < 16; c++) Or[c] = 0.0f;
        if (tid < 64) { m_s[tid] = -1e30f; l_s[tid] = 0.0f; }
    }
    __syncthreads();

    for (int j0 = 0; j0 < TENC; j0 += 64) {
        // Load K and V tiles (64x64 each)
        #pragma unroll
        for (int i = tid; i < 1024; i += 256) {
            int row = i >> 4, c4 = i & 15;
            size_t g = (size_t)(b * TENC + j0 + row) * DM + h * DH + c4 * 4;
            float4 kv = *reinterpret_cast<const float4*>(&K[g]);
            float4 vv = *reinterpret_cast<const float4*>(&V[g]);
            float* kd = &Ks[row * ATT_LD + c4 * 4];
            float* vd = &Vs[row * ATT_LD + c4 * 4];
            kd[0] = kv.x; kd[1] = kv.y; kd[2] = kv.z; kd[3] = kv.w;
            vd[0] = vv.x; vd[1] = vv.y; vd[2] = vv.z; vd[3] = vv.w;
        }
        __syncthreads();

        // S = Qs @ Ks^T  (64x64x64), warp tile 16x32
        {
            wmma::fragment<wmma::accumulator, 16, 16, 8, float> sacc[2];
            wmma::fill_fragment(sacc[0], 0.0f);
            wmma::fill_fragment(sacc[1], 0.0f);
            #pragma unroll
            for (int kk = 0; kk < 64; kk += 8) {
                wmma::fragment<wmma::matrix_a, 16, 16, 8, wmma::precision::tf32, wmma::row_major> afr;
                wmma::load_matrix_sync(afr, &Qs[(wm * 16) * ATT_LD + kk], ATT_LD);
                #pragma unroll
                for (int e = 0; e < afr.num_elements; e++)
                    afr.x[e] = wmma::__float_to_tf32(afr.x[e]);
                #pragma unroll
                for (int nt = 0; nt < 2; nt++) {
                    wmma::fragment<wmma::matrix_b, 16, 16, 8, wmma::precision::tf32, wmma::col_major> bfr;
                    wmma::load_matrix_sync(bfr, &Ks[(wn * 32 + nt * 16) * ATT_LD + kk], ATT_LD);
                    #pragma unroll
                    for (int e = 0; e < bfr.num_elements; e++)
                        bfr.x[e] = wmma::__float_to_tf32(bfr.x[e]);
                    wmma::mma_sync(sacc[nt], afr, bfr, sacc[nt]);
                }
            }
            #pragma unroll
            for (int nt = 0; nt < 2; nt++)
                wmma::store_matrix_sync(&Ss[(wm * 16) * ATT_LD + wn * 32 + nt * 16],
                                        sacc[nt], ATT_LD, wmma::mem_row_major);
        }
        __syncthreads();

        // Online softmax: 4 threads per row, 16 cols each
        {
            int r = tid >> 2, seg = tid & 3;
            float* Sr = &Ss[r * ATT_LD + seg * 16];
            float mx = -1e30f;
            #pragma unroll
            for (int c = 0; c < 16; c++) mx = fmaxf(mx, Sr[c]);
            mx = fmaxf(mx, __shfl_xor_sync(0xffffffffu, mx, 1));
            mx = fmaxf(mx, __shfl_xor_sync(0xffffffffu, mx, 2));
            float mold = m_s[r];
            float mnew = fmaxf(mold, mx);
            float alpha = __expf(mold - mnew);
            float sum = 0.0f;
            #pragma unroll
            for (int c = 0; c < 16; c++) {
                float p = __expf(Sr[c] - mnew);
                Sr[c] = p;
                sum += p;
            }
            sum += __shfl_xor_sync(0xffffffffu, sum, 1);
            sum += __shfl_xor_sync(0xffffffffu, sum, 2);
            float* Or = &Os[r * ATT_LD + seg * 16];
            #pragma unroll
            for (int c = 0; c < 16; c++) Or[c] *= alpha;
            if (seg == 0) {
                m_s[r] = mnew;
                l_s[r] = l_s[r] * alpha + sum;
            }
        }
        __syncthreads();

        // O += P @ V (64x64x64), warp tile 16x32, accumulate in place
        {
            #pragma unroll
            for (int nt = 0; nt < 2; nt++) {
                wmma::fragment<wmma::accumulator, 16, 16, 8, float> oacc;
                wmma::load_matrix_sync(oacc, &Os[(wm * 16) * ATT_LD + wn * 32 + nt * 16],
                                       ATT_LD, wmma::mem_row_major);
                #pragma unroll
                for (int kk = 0; kk < 64; kk += 8) {
                    wmma::fragment<wmma::matrix_a, 16, 16, 8, wmma::precision::tf32, wmma::row_major> afr;
                    wmma::load_matrix_sync(afr, &Ss[(wm * 16) * ATT_LD + kk], ATT_LD);
                    #pragma unroll
                    for (int e = 0; e < afr.num_elements; e++)
                        afr.x[e] = wmma::__float_to_tf32(afr.x[e]);
                    wmma::fragment<wmma::matrix_b, 16, 16, 8, wmma::precision::tf32, wmma::row_major> bfr;
                    wmma::load_matrix_sync(bfr, &Vs[kk * ATT_LD + wn * 32 + nt * 16], ATT_LD);
                    #pragma unroll
                    for (int e = 0; e < bfr.num_elements; e++)
                        bfr.x[e] = wmma::__float_to_tf32(bfr.x[e]);
                    wmma::mma_sync(oacc, afr, bfr, oacc);
                }
                wmma::store_matrix_sync(&Os[(wm * 16) * ATT_LD + wn * 32 + nt * 16],
                                        oacc, ATT_LD, wmma::mem_row_major);
            }
        }
        __syncthreads();
    }

    // Epilogue: Y[b, q0+r, h*64 + d] = Os[r][d] / l[r]
    {
        int r = tid >> 2, seg = tid & 3;
        float inv_l = 1.0f / l_s[r];
        const float* Or = &Os[r * ATT_LD + seg * 16];
        float* dst = &Y[(size_t)(b * TDEC + q0 + r) * DM + h * DH + seg * 16];
        #pragma unroll
        for (int c4 = 0; c4 < 4; c4++) {
            float4 v;
            v.x = Or[c4 * 4 + 0] * inv_l;
            v.y = Or[c4 * 4 + 1] * inv_l;
            v.z = Or[c4 * 4 + 2] * inv_l;
            v.w = Or[c4 * 4 + 3] * inv_l;
            *reinterpret_cast<float4*>(&dst[c4 * 4]) = v;
        }
    }
}

// ---------------------------------------------------------------------------
// Launcher
// ---------------------------------------------------------------------------
extern "C" void kernel_launch(void* const* d_in, const int* in_sizes, int n_in,
                              void* d_out, int out_size)
{
    const float* tgt    = (const float*)d_in[0];
    const float* memory = (const float*)d_in[1];
    const float* W_q    = (const float*)d_in[2];
    const float* b_q    = (const float*)d_in[3];
    const float* W_k    = (const float*)d_in[4];
    const float* b_k    = (const float*)d_in[5];
    const float* W_v    = (const float*)d_in[6];
    const float* b_v    = (const float*)d_in[7];
    const float* W_o    = (const float*)d_in[8];
    const float* b_o    = (const float*)d_in[9];
    float* out = (float*)d_out;

    float *gQ, *gK, *gV, *gY;
    cudaGetSymbolAddress((void**)&gQ, g_Q);
    cudaGetSymbolAddress((void**)&gK, g_K);
    cudaGetSymbolAddress((void**)&gV, g_V);
    cudaGetSymbolAddress((void**)&gY, g_Y);

    dim3 ggrid(DM / 128, BT / 128);   // (8, 32)
    const int total = BT * DM;

    // Projections
    gemm_tf32_kernel<<<ggrid, 256>>>(tgt,    W_q, gQ, BT, DM, DM);
    gemm_tf32_kernel<<<ggrid, 256>>>(memory, W_k, gK, BT, DM, DM);
    gemm_tf32_kernel<<<ggrid, 256>>>(memory, W_v, gV, BT, DM, DM);
    bias_kernel<<<2048, 256>>>(gQ, b_q, total);
    bias_kernel<<<2048, 256>>>(gK, b_k, total);
    bias_kernel<<<2048, 256>>>(gV, b_v, total);

    // Attention
    cudaFuncSetAttribute(attn_kernel, cudaFuncAttributeMaxDynamicSharedMemorySize,
                         ATT_SMEM_BYTES);
    attn_kernel<<<dim3(TDEC / 64, NB * NHEADS), 256, ATT_SMEM_BYTES>>>(gQ, gK, gV, gY);

    // Output projection
    gemm_tf32_kernel<<<ggrid, 256>>>(gY, W_o, out, BT, DM, DM);
    bias_kernel<<<2048, 256>>>(out, b_o, total);
}

// round 3
// speedup vs baseline: 1.1900x; 1.1900x over previous
#include <cuda_runtime.h>
#include <mma.h>
using namespace nvcuda;

// Problem constants (fixed by the reference)
#define BT      4096      // B * T_dec = B * T_enc = 2 * 2048
#define DM      1024      // d_model
#define NHEADS  16
#define DH      64
#define TDEC    2048
#define TENC    2048
#define NB      2

// Scratch (allocation-free): Q, K, V, Y buffers, each (4096 x 1024) fp32
__device__ float g_Q[BT * DM];
__device__ float g_K[BT * DM];
__device__ float g_V[BT * DM];
__device__ float g_Y[BT * DM];

// ---------------------------------------------------------------------------
// cp.async helpers
// ---------------------------------------------------------------------------
__device__ __forceinline__ void cp_async16(void* smem_dst, const void* gmem_src) {
    unsigned sa = (unsigned)__cvta_generic_to_shared(smem_dst);
    asm volatile("cp.async.cg.shared.global [%0], [%1], 16;\n" :: "r"(sa), "l"(gmem_src));
}
__device__ __forceinline__ void cp_commit() {
    asm volatile("cp.async.commit_group;\n");
}
__device__ __forceinline__ void cp_wait_all() {
    asm volatile("cp.async.wait_group 0;\n");
}
__device__ __forceinline__ float tf32_round(float v) {
    unsigned t;
    asm("cvt.rna.tf32.f32 %0, %1;" : "=r"(t) : "f"(v));
    return __uint_as_float(t);
}

// ---------------------------------------------------------------------------
// TF32 tiled GEMM, double-buffered via cp.async.
// C = X @ W (X: MxK row-major, W: KxN row-major). Tile 128x128x16, 8 warps.
// ---------------------------------------------------------------------------
#define GLDA 24     // 16 + 8 pad
#define GLDB 136    // 128 + 8 pad

__global__ __launch_bounds__(256) void gemm_tf32_kernel(
    const float* __restrict__ X, const float* __restrict__ W,
    float* __restrict__ C, int M, int N, int K)
{
    __shared__ float As[2][128 * GLDA];
    __shared__ float Bs[2][16 * GLDB];

    const int bm = blockIdx.y * 128;
    const int bn = blockIdx.x * 128;
    const int tid = threadIdx.x;
    const int warp = tid >> 5;
    const int wm = warp >> 1;   // 0..3 -> row block of 32
    const int wn = warp & 1;    // 0..1 -> col block of 64

    wmma::fragment<wmma::accumulator, 16, 16, 8, float> acc[2][4];
    #pragma unroll
    for (int i = 0; i < 2; i++)
        #pragma unroll
        for (int j = 0; j < 4; j++)
            wmma::fill_fragment(acc[i][j], 0.0f);

    // stage loader: A tile 128x16, B tile 16x128 (512 float4 each, 2/thread)
    auto load_stage = [&](int s, int k0) {
        #pragma unroll
        for (int i = tid; i < 512; i += 256) {
            int row = i >> 2, c4 = i & 3;
            cp_async16(&As[s][row * GLDA + c4 * 4],
                       &X[(size_t)(bm + row) * K + k0 + c4 * 4]);
        }
        #pragma unroll
        for (int i = tid; i < 512; i += 256) {
            int row = i >> 5, c4 = i & 31;
            cp_async16(&Bs[s][row * GLDB + c4 * 4],
                       &W[(size_t)(k0 + row) * N + bn + c4 * 4]);
        }
        cp_commit();
    };

    const int nk = K / 16;
    load_stage(0, 0);

    for (int kt = 0; kt < nk; kt++) {
        cp_wait_all();
        __syncthreads();
        if (kt + 1 < nk) load_stage((kt + 1) & 1, (kt + 1) * 16);
        const int s = kt & 1;

        #pragma unroll
        for (int kk = 0; kk < 16; kk += 8) {
            wmma::fragment<wmma::matrix_a, 16, 16, 8, wmma::precision::tf32, wmma::row_major> afr[2];
            wmma::fragment<wmma::matrix_b, 16, 16, 8, wmma::precision::tf32, wmma::row_major> bfr[4];
            #pragma unroll
            for (int mt = 0; mt < 2; mt++) {
                wmma::load_matrix_sync(afr[mt], &As[s][(wm * 32 + mt * 16) * GLDA + kk], GLDA);
                #pragma unroll
                for (int e = 0; e < afr[mt].num_elements; e++)
                    afr[mt].x[e] = wmma::__float_to_tf32(afr[mt].x[e]);
            }
            #pragma unroll
            for (int nt = 0; nt < 4; nt++) {
                wmma::load_matrix_sync(bfr[nt], &Bs[s][kk * GLDB + wn * 64 + nt * 16], GLDB);
                #pragma unroll
                for (int e = 0; e < bfr[nt].num_elements; e++)
                    bfr[nt].x[e] = wmma::__float_to_tf32(bfr[nt].x[e]);
            }
            #pragma unroll
            for (int mt = 0; mt < 2; mt++)
                #pragma unroll
                for (int nt = 0; nt < 4; nt++)
                    wmma::mma_sync(acc[mt][nt], afr[mt], bfr[nt], acc[mt][nt]);
        }
        // no trailing barrier: next iteration's wait+sync protects stage reuse
    }

    #pragma unroll
    for (int mt = 0; mt < 2; mt++)
        #pragma unroll
        for (int nt = 0; nt < 4; nt++)
            wmma::store_matrix_sync(
                &C[(size_t)(bm + wm * 32 + mt * 16) * N + bn + wn * 64 + nt * 16],
                acc[mt][nt], N, wmma::mem_row_major);
}

// ---------------------------------------------------------------------------
// Bias add (+ optional round-to-tf32 so attention can skip F2FP entirely)
// ---------------------------------------------------------------------------
__global__ void bias_round_kernel(float* __restrict__ C, const float* __restrict__ b, int total)
{
    for (int idx = blockIdx.x * blockDim.x + threadIdx.x; idx < total;
         idx += gridDim.x * blockDim.x)
        C[idx] = tf32_round(C[idx] + b[idx & (DM - 1)]);
}

__global__ void bias_kernel(float* __restrict__ C, const float* __restrict__ b, int total)
{
    for (int idx = blockIdx.x * blockDim.x + threadIdx.x; idx < total;
         idx += gridDim.x * blockDim.x)
        C[idx] += b[idx & (DM - 1)];
}

// ---------------------------------------------------------------------------
// Flash attention, TF32 wmma, K-chunk = 128, cp.async double-buffered K/V.
// One block = one (b,h) x 64 query rows. grid = (TDEC/64, B*NHEADS), 256 thr.
// All inputs pre-rounded to tf32 -> no fragment conversions in the mainloop.
// ---------------------------------------------------------------------------
#define KC      128
#define ALD     72    // 64 + 8
#define SLD     136   // 128 + 8
#define NJT     (TENC / KC)

// smem floats: Qs 4608 | Os 4608 | Ss 8704 | Ks[2] 18432 | Vs[2] 18432 | m 64 | l 64
#define ATT_SMEM_BYTES ((4608 + 4608 + 8704 + 18432 + 18432 + 128) * 4)

__global__ __launch_bounds__(256) void attn_kernel(
    const float* __restrict__ Q, const float* __restrict__ K,
    const float* __restrict__ V, float* __restrict__ Y)
{
    extern __shared__ float sm[];
    float* Qs  = sm;                    // 64 x ALD
    float* Os  = Qs + 64 * ALD;         // 64 x ALD
    float* Ss  = Os + 64 * ALD;         // 64 x SLD
    float* Ks0 = Ss + 64 * SLD;         // [2][KC x ALD]
    float* Vs0 = Ks0 + 2 * KC * ALD;    // [2][KC x ALD]
    float* m_s = Vs0 + 2 * KC * ALD;    // 64
    float* l_s = m_s + 64;              // 64

    const int bh = blockIdx.y;
    const int b  = bh >> 4;             // NHEADS = 16
    const int h  = bh & 15;
    const int q0 = blockIdx.x * 64;
    const int tid = threadIdx.x;
    const int warp = tid >> 5;
    const int wm = warp >> 1;           // 0..3 -> 16-row stripe
    const int wn = warp & 1;            // 0..1 -> col half
    const float scale = 0.125f;         // 1/sqrt(64); pow2 keeps tf32 exact

    // prefetch K/V chunk jt into stage s (128 rows x 64 cols, both tensors)
    auto prefetch_kv = [&](int s, int jt) {
        float* Ks = Ks0 + s * KC * ALD;
        float* Vs = Vs0 + s * KC * ALD;
        const int j0 = jt * KC;
        #pragma unroll
        for (int i = tid; i < 2048; i += 256) {
            int row = i >> 4, c4 = i & 15;
            size_t g = (size_t)(b * TENC + j0 + row) * DM + h * DH + c4 * 4;
            cp_async16(&Ks[row * ALD + c4 * 4], &K[g]);
            cp_async16(&Vs[row * ALD + c4 * 4], &V[g]);
        }
        cp_commit();
    };

    // Load Q tile (64x64), pre-scaled (values are tf32; x0.125 stays tf32)
    #pragma unroll
    for (int i = tid; i < 1024; i += 256) {
        int row = i >> 4, c4 = i & 15;
        float4 v = *reinterpret_cast<const float4*>(
            &Q[(size_t)(b * TDEC + q0 + row) * DM + h * DH + c4 * 4]);
        float* dst = &Qs[row * ALD + c4 * 4];
        dst[0] = v.x * scale; dst[1] = v.y * scale;
        dst[2] = v.z * scale; dst[3] = v.w * scale;
    }
    // Init O accumulator + stats
    {
        int r = tid >> 2, seg = tid & 3;
        float* Or = &Os[r * ALD + seg * 16];
        #pragma unroll
        for (int c = 0; c < 16; c++) Or[c] = 0.0f;
        if (tid < 64) { m_s[tid] = -1e30f; l_s[tid] = 0.0f; }
    }
    prefetch_kv(0, 0);

    for (int jt = 0; jt < NJT; jt++) {
        cp_wait_all();
        __syncthreads();                 // stage jt&1 ready; prior iter's smem reads done
        if (jt + 1 < NJT) prefetch_kv((jt + 1) & 1, jt + 1);
        const int st = jt & 1;
        float* Ks = Ks0 + st * KC * ALD;
        float* Vs = Vs0 + st * KC * ALD;

        // ---- S = Qs @ Ks^T : 64 x 128, warp tile 16 x 64 ----
        {
            wmma::fragment<wmma::accumulator, 16, 16, 8, float> sacc[4];
            #pragma unroll
            for (int nt = 0; nt < 4; nt++) wmma::fill_fragment(sacc[nt], 0.0f);
            #pragma unroll
            for (int kk = 0; kk < 64; kk += 8) {
                wmma::fragment<wmma::matrix_a, 16, 16, 8, wmma::precision::tf32, wmma::row_major> afr;
                wmma::load_matrix_sync(afr, &Qs[(wm * 16) * ALD + kk], ALD);
                #pragma unroll
                for (int nt = 0; nt < 4; nt++) {
                    wmma::fragment<wmma::matrix_b, 16, 16, 8, wmma::precision::tf32, wmma::col_major> bfr;
                    wmma::load_matrix_sync(bfr, &Ks[(wn * 64 + nt * 16) * ALD + kk], ALD);
                    wmma::mma_sync(sacc[nt], afr, bfr, sacc[nt]);
                }
            }
            #pragma unroll
            for (int nt = 0; nt < 4; nt++)
                wmma::store_matrix_sync(&Ss[(wm * 16) * SLD + wn * 64 + nt * 16],
                                        sacc[nt], SLD, wmma::mem_row_major);
        }
        __syncthreads();

        // ---- online softmax: 4 threads/row, 32 strided cols each ----
        {
            int r = tid >> 2, seg = tid & 3;
            float* Sr = &Ss[r * SLD];
            float mx = -1e30f;
            #pragma unroll
            for (int c = 0; c < 32; c++) mx = fmaxf(mx, Sr[seg + 4 * c]);
            mx = fmaxf(mx, __shfl_xor_sync(0xffffffffu, mx, 1));
            mx = fmaxf(mx, __shfl_xor_sync(0xffffffffu, mx, 2));
            float mold = m_s[r];
            float mnew = fmaxf(mold, mx);
            float alpha = __expf(mold - mnew);
            float sum = 0.0f;
            #pragma unroll
            for (int c = 0; c < 32; c++) {
                float p = __expf(Sr[seg + 4 * c] - mnew);
                sum += p;
                Sr[seg + 4 * c] = tf32_round(p);   // P fed to tensor cores as-is
            }
            sum += __shfl_xor_sync(0xffffffffu, sum, 1);
            sum += __shfl_xor_sync(0xffffffffu, sum, 2);
            float* Or = &Os[r * ALD + seg * 16];
            #pragma unroll
            for (int c = 0; c < 16; c++) Or[c] *= alpha;
            if (seg == 0) {
                m_s[r] = mnew;
                l_s[r] = l_s[r] * alpha + sum;
            }
        }
        __syncthreads();

        // ---- O += P @ V : 64 x 64 += (64x128)@(128x64), warp tile 16x32 ----
        {
            wmma::fragment<wmma::accumulator, 16, 16, 8, float> oacc[2];
            #pragma unroll
            for (int nt = 0; nt < 2; nt++)
                wmma::load_matrix_sync(oacc[nt], &Os[(wm * 16) * ALD + wn * 32 + nt * 16],
                                       ALD, wmma::mem_row_major);
            #pragma unroll
            for (int kk = 0; kk < KC; kk += 8) {
                wmma::fragment<wmma::matrix_a, 16, 16, 8, wmma::precision::tf32, wmma::row_major> afr;
                wmma::load_matrix_sync(afr, &Ss[(wm * 16) * SLD + kk], SLD);
                #pragma unroll
                for (int nt = 0; nt < 2; nt++) {
                    wmma::fragment<wmma::matrix_b, 16, 16, 8, wmma::precision::tf32, wmma::row_major> bfr;
                    wmma::load_matrix_sync(bfr, &Vs[kk * ALD + wn * 32 + nt * 16], ALD);
                    wmma::mma_sync(oacc[nt], afr, bfr, oacc[nt]);
                }
            }
            #pragma unroll
            for (int nt = 0; nt < 2; nt++)
                wmma::store_matrix_sync(&Os[(wm * 16) * ALD + wn * 32 + nt * 16],
                                        oacc[nt], ALD, wmma::mem_row_major);
        }
        // no trailing barrier: next iteration's top barrier protects Ss/Os
    }
    __syncthreads();

    // Epilogue: Y[b, q0+r, h*64 + d] = Os[r][d] / l[r]
    {
        int r = tid >> 2, seg = tid & 3;
        float inv_l = 1.0f / l_s[r];
        const float* Or = &Os[r * ALD + seg * 16];
        float* dst = &Y[(size_t)(b * TDEC + q0 + r) * DM + h * DH + seg * 16];
        #pragma unroll
        for (int c4 = 0; c4 < 4; c4++) {
            float4 v;
            v.x = Or[c4 * 4 + 0] * inv_l;
            v.y = Or[c4 * 4 + 1] * inv_l;
            v.z = Or[c4 * 4 + 2] * inv_l;
            v.w = Or[c4 * 4 + 3] * inv_l;
            *reinterpret_cast<float4*>(&dst[c4 * 4]) = v;
        }
    }
}

// ---------------------------------------------------------------------------
// Launcher
// ---------------------------------------------------------------------------
extern "C" void kernel_launch(void* const* d_in, const int* in_sizes, int n_in,
                              void* d_out, int out_size)
{
    const float* tgt    = (const float*)d_in[0];
    const float* memory = (const float*)d_in[1];
    const float* W_q    = (const float*)d_in[2];
    const float* b_q    = (const float*)d_in[3];
    const float* W_k    = (const float*)d_in[4];
    const float* b_k    = (const float*)d_in[5];
    const float* W_v    = (const float*)d_in[6];
    const float* b_v    = (const float*)d_in[7];
    const float* W_o    = (const float*)d_in[8];
    const float* b_o    = (const float*)d_in[9];
    float* out = (float*)d_out;

    float *gQ, *gK, *gV, *gY;
    cudaGetSymbolAddress((void**)&gQ, g_Q);
    cudaGetSymbolAddress((void**)&gK, g_K);
    cudaGetSymbolAddress((void**)&gV, g_V);
    cudaGetSymbolAddress((void**)&gY, g_Y);

    dim3 ggrid(DM / 128, BT / 128);   // (8, 32)
    const int total = BT * DM;

    // Projections (+ bias + round-to-tf32 so attention skips conversions)
    gemm_tf32_kernel<<<ggrid, 256>>>(tgt,    W_q, gQ, BT, DM, DM);
    gemm_tf32_kernel<<<ggrid, 256>>>(memory, W_k, gK, BT, DM, DM);
    gemm_tf32_kernel<<<ggrid, 256>>>(memory, W_v, gV, BT, DM, DM);
    bias_round_kernel<<<2048, 256>>>(gQ, b_q, total);
    bias_round_kernel<<<2048, 256>>>(gK, b_k, total);
    bias_round_kernel<<<2048, 256>>>(gV, b_v, total);

    // Attention
    cudaFuncSetAttribute(attn_kernel, cudaFuncAttributeMaxDynamicSharedMemorySize,
                         ATT_SMEM_BYTES);
    attn_kernel<<<dim3(TDEC / 64, NB * NHEADS), 256, ATT_SMEM_BYTES>>>(gQ, gK, gV, gY);

    // Output projection
    gemm_tf32_kernel<<<ggrid, 256>>>(gY, W_o, out, BT, DM, DM);
    bias_kernel<<<2048, 256>>>(out, b_o, total);
}